// round 6
// baseline (speedup 1.0000x reference)
#include <cuda_runtime.h>
#include <cuda_fp16.h>
#include <cuda_bf16.h>

#define HINGES 1024
#define UNROLL 8

// out(x) = P + S*(x - c*delta), c = ceil(x/delta), table indexed t = clamp(c+511).
// P anchored at x0 = c*delta (fp32 build, fp16 store). Tails via exact selects
// (bins t=0 / t=1023 are shared with in-range wrap/extrapolation bins, so the
// tails cannot be folded into the table).
__device__ __forceinline__ float adact1(float xv, const __half2* __restrict__ tabh,
                                        float r, float s, float delta, float inv_delta,
                                        float a0, float aL) {
    float q  = __fmul_rn(xv, inv_delta);
    float cf = ceilf(q);
    int   c  = (int)cf;
    int   t  = min(max(c + 511, 0), HINGES - 1);
    float2 ps = __half22float2(tabh[t]);     // one LDS.32
    float xa = __fmaf_rn(-delta, cf, xv);    // x - c*delta
    float v  = __fmaf_rn(ps.y, xa, ps.x);
    v = (xv < r) ? a0 : v;
    v = (xv > s) ? aL : v;
    return v;
}

__global__ __launch_bounds__(256, 6)
void adact_kernel(const float4* __restrict__ x,
                  const float*  __restrict__ ns,
                  const float*  __restrict__ a,
                  float4* __restrict__ out, int n4) {
    __shared__ __half2 tabh[HINGES];         // 4 KB (P,S) per bin

    const float r     = ns[0];
    const float s     = ns[HINGES - 1];
    const float a0    = a[0];
    const float aL    = a[HINGES - 1];
    const float delta = __fadd_rn(ns[1], -ns[0]);
    const float inv_delta = __fdiv_rn(1.0f, delta);

    // Build anchored-affine table (reference clamp+wrap logic, fp32).
    #pragma unroll
    for (int t = threadIdx.x; t < HINGES; t += 256) {
        int c  = t - 511;
        int m1 = max(c - 1, 0);
        m1 = min(m1, HINGES - 1);
        int m2 = c;
        if (m2 >= HINGES) m2 = HINGES - 1;
        if (m2 < 0)       m2 += HINGES;
        m2 = min(max(m2, 0), HINGES - 1);

        float ns1 = ns[m1], ns2 = ns[m2];
        float a1  = a[m1],  a2  = a[m2];
        float denom = __fadd_rn(ns2, -ns1);
        denom = (denom == 0.0f) ? 1.0f : denom;

        float x0 = __fmul_rn((float)c, delta);
        float w1 = __fdiv_rn(__fadd_rn(ns2, -x0), denom);
        float w2 = __fdiv_rn(__fadd_rn(x0, -ns1), denom);
        float P  = __fadd_rn(__fmul_rn(w1, a1), __fmul_rn(w2, a2));
        float S  = __fdiv_rn(__fadd_rn(a2, -a1), denom);
        tabh[t] = __floats2half2_rn(P, S);
    }
    __syncthreads();

    // Main loop: 8 front-batched LDG.128s per iteration (MLP=8), so the
    // per-iteration DRAM wait amortizes over 32 elements.
    const int stride = gridDim.x * 256;
    int idx = blockIdx.x * 256 + threadIdx.x;

    for (; idx + (UNROLL - 1) * stride < n4; idx += UNROLL * stride) {
        float4 v[UNROLL];
        #pragma unroll
        for (int k = 0; k < UNROLL; k++)
            v[k] = __ldcs(&x[idx + k * stride]);

        #pragma unroll
        for (int k = 0; k < UNROLL; k++) {
            float4 o;
            o.x = adact1(v[k].x, tabh, r, s, delta, inv_delta, a0, aL);
            o.y = adact1(v[k].y, tabh, r, s, delta, inv_delta, a0, aL);
            o.z = adact1(v[k].z, tabh, r, s, delta, inv_delta, a0, aL);
            o.w = adact1(v[k].w, tabh, r, s, delta, inv_delta, a0, aL);
            __stcs(&out[idx + k * stride], o);
        }
    }
    // Remainder.
    for (; idx < n4; idx += stride) {
        float4 v = __ldcs(&x[idx]);
        float4 o;
        o.x = adact1(v.x, tabh, r, s, delta, inv_delta, a0, aL);
        o.y = adact1(v.y, tabh, r, s, delta, inv_delta, a0, aL);
        o.z = adact1(v.z, tabh, r, s, delta, inv_delta, a0, aL);
        o.w = adact1(v.w, tabh, r, s, delta, inv_delta, a0, aL);
        __stcs(&out[idx], o);
    }
}

extern "C" void kernel_launch(void* const* d_in, const int* in_sizes, int n_in,
                              void* d_out, int out_size) {
    const float* x  = (const float*)d_in[0];
    const float* ns = (const float*)d_in[1];
    const float* a  = (const float*)d_in[2];
    float* out = (float*)d_out;

    int n  = in_sizes[0];
    int n4 = n >> 2;

    int blocks = (n4 + 255) / 256;
    const int max_blocks = 148 * 6;          // one wave @ 6 CTAs/SM
    if (blocks > max_blocks) blocks = max_blocks;

    adact_kernel<<<blocks, 256>>>((const float4*)x, ns, a, (float4*)out, n4);
}

// round 7
// speedup vs baseline: 1.1919x; 1.1919x over previous
#include <cuda_runtime.h>
#include <cuda_fp16.h>
#include <cuda_bf16.h>

#define HINGES 1024
#define UNROLL 4
#define PF_ITERS 4   // prefetch distance in grid-stride iterations

// out(x) = P + S*(x - c*delta), c = ceil(x/delta), t = clamp(c+511, 0, 1023).
// (P,S) built in fp32 replicating the reference clamp+wrap gather semantics,
// stored fp16 (P anchored at x0 = c*delta so fp16 error is output-relative).
// Tails handled by exact fp32 selects.
__device__ __forceinline__ float adact1(float xv, const __half2* __restrict__ tabh,
                                        float r, float s, float delta, float inv_delta,
                                        float a0, float aL) {
    float q  = __fmul_rn(xv, inv_delta);
    float cf = ceilf(q);
    int   c  = (int)cf;
    int   t  = min(max(c + 511, 0), HINGES - 1);
    float2 ps = __half22float2(tabh[t]);     // one LDS.32
    float xa = __fmaf_rn(-delta, cf, xv);    // x - c*delta
    float v  = __fmaf_rn(ps.y, xa, ps.x);
    v = (xv < r) ? a0 : v;
    v = (xv > s) ? aL : v;
    return v;
}

__global__ __launch_bounds__(256, 8)
void adact_kernel(const float4* __restrict__ x,
                  const float*  __restrict__ ns,
                  const float*  __restrict__ a,
                  float4* __restrict__ out, int n4) {
    __shared__ __half2 tabh[HINGES];         // 4 KB (P,S) per bin

    const float r     = ns[0];
    const float s     = ns[HINGES - 1];
    const float a0    = a[0];
    const float aL    = a[HINGES - 1];
    const float delta = __fadd_rn(ns[1], -ns[0]);
    const float inv_delta = __fdiv_rn(1.0f, delta);

    // Build anchored-affine table (reference clamp+wrap logic, fp32).
    #pragma unroll
    for (int t = threadIdx.x; t < HINGES; t += 256) {
        int c  = t - 511;
        int m1 = max(c - 1, 0);
        m1 = min(m1, HINGES - 1);
        int m2 = c;
        if (m2 >= HINGES) m2 = HINGES - 1;
        if (m2 < 0)       m2 += HINGES;
        m2 = min(max(m2, 0), HINGES - 1);

        float ns1 = ns[m1], ns2 = ns[m2];
        float a1  = a[m1],  a2  = a[m2];
        float denom = __fadd_rn(ns2, -ns1);
        denom = (denom == 0.0f) ? 1.0f : denom;

        float x0 = __fmul_rn((float)c, delta);
        float w1 = __fdiv_rn(__fadd_rn(ns2, -x0), denom);
        float w2 = __fdiv_rn(__fadd_rn(x0, -ns1), denom);
        float P  = __fadd_rn(__fmul_rn(w1, a1), __fmul_rn(w2, a2));
        float S  = __fdiv_rn(__fadd_rn(a2, -a1), denom);
        tabh[t] = __floats2half2_rn(P, S);
    }
    __syncthreads();

    // Main loop: 4 front-batched LDG.128s (R3 winner config: 32 regs, 64 warps/SM)
    // + per-thread L2 prefetch PF_ITERS iterations ahead (no regs, no tracking):
    // demand loads then hit L2 (~250 cyc) instead of DRAM (~600 cyc).
    const int stride = gridDim.x * 256;
    int idx = blockIdx.x * 256 + threadIdx.x;

    for (; idx + 3 * stride < n4; idx += 4 * stride) {
        // L2 prefetch for the iteration PF_ITERS ahead (first of its 4 loads
        // covers the same lines pattern; prefetch all 4 future segments).
        #pragma unroll
        for (int k = 0; k < UNROLL; k++) {
            int pidx = idx + (PF_ITERS * UNROLL + k) * stride;
            if (pidx < n4)
                asm volatile("prefetch.global.L2 [%0];" :: "l"(&x[pidx]));
        }

        float4 v0 = __ldcs(&x[idx]);
        float4 v1 = __ldcs(&x[idx + stride]);
        float4 v2 = __ldcs(&x[idx + 2 * stride]);
        float4 v3 = __ldcs(&x[idx + 3 * stride]);

        float4 o0, o1, o2, o3;
        o0.x = adact1(v0.x, tabh, r, s, delta, inv_delta, a0, aL);
        o0.y = adact1(v0.y, tabh, r, s, delta, inv_delta, a0, aL);
        o0.z = adact1(v0.z, tabh, r, s, delta, inv_delta, a0, aL);
        o0.w = adact1(v0.w, tabh, r, s, delta, inv_delta, a0, aL);
        o1.x = adact1(v1.x, tabh, r, s, delta, inv_delta, a0, aL);
        o1.y = adact1(v1.y, tabh, r, s, delta, inv_delta, a0, aL);
        o1.z = adact1(v1.z, tabh, r, s, delta, inv_delta, a0, aL);
        o1.w = adact1(v1.w, tabh, r, s, delta, inv_delta, a0, aL);
        o2.x = adact1(v2.x, tabh, r, s, delta, inv_delta, a0, aL);
        o2.y = adact1(v2.y, tabh, r, s, delta, inv_delta, a0, aL);
        o2.z = adact1(v2.z, tabh, r, s, delta, inv_delta, a0, aL);
        o2.w = adact1(v2.w, tabh, r, s, delta, inv_delta, a0, aL);
        o3.x = adact1(v3.x, tabh, r, s, delta, inv_delta, a0, aL);
        o3.y = adact1(v3.y, tabh, r, s, delta, inv_delta, a0, aL);
        o3.z = adact1(v3.z, tabh, r, s, delta, inv_delta, a0, aL);
        o3.w = adact1(v3.w, tabh, r, s, delta, inv_delta, a0, aL);

        __stcs(&out[idx],              o0);
        __stcs(&out[idx + stride],     o1);
        __stcs(&out[idx + 2 * stride], o2);
        __stcs(&out[idx + 3 * stride], o3);
    }
    for (; idx < n4; idx += stride) {
        float4 v = __ldcs(&x[idx]);
        float4 o;
        o.x = adact1(v.x, tabh, r, s, delta, inv_delta, a0, aL);
        o.y = adact1(v.y, tabh, r, s, delta, inv_delta, a0, aL);
        o.z = adact1(v.z, tabh, r, s, delta, inv_delta, a0, aL);
        o.w = adact1(v.w, tabh, r, s, delta, inv_delta, a0, aL);
        __stcs(&out[idx], o);
    }
}

extern "C" void kernel_launch(void* const* d_in, const int* in_sizes, int n_in,
                              void* d_out, int out_size) {
    const float* x  = (const float*)d_in[0];
    const float* ns = (const float*)d_in[1];
    const float* a  = (const float*)d_in[2];
    float* out = (float*)d_out;

    int n  = in_sizes[0];
    int n4 = n >> 2;

    int blocks = (n4 + 255) / 256;
    const int max_blocks = 148 * 8;          // one wave @ 8 CTAs/SM
    if (blocks > max_blocks) blocks = max_blocks;

    adact_kernel<<<blocks, 256>>>((const float4*)x, ns, a, (float4*)out, n4);
}